// round 13
// baseline (speedup 1.0000x reference)
#include <cuda_runtime.h>
#include <math.h>

#define D_MODEL 32
#define NHEAD 4
#define WIN 256
#define HWIN 128
#define DFF 64
#define INDIM 58
#define HOUT 25
#define NLAYER 4

// ---- shared memory layout (floats) ----
#define L_IPW  0      // 96*32
#define L_IPB  3072   // 96
#define L_OPW  3168   // 32*32
#define L_OPB  4192   // 32
#define L_G1   4224
#define L_B1   4256
#define L_W1   4288   // 64*32
#define L_BB1  6336   // 64
#define L_W2T  6400   // 64*32 (transposed lin2_w)
#define L_BB2  8448
#define L_G2   8480
#define L_B2   8512

// embedding overlay
#define E_FPW  0      // 32*58
#define E_FPB  1856
#define E_LEMB 1888   // 12*32
#define E_FB   2272   // 3*16

// head overlay
#define H_NOG  0
#define H_NOB  32
#define H_HW   64     // 25*32
#define H_HB   864

#define KV_STRIDE 36
#define OFF_K  8544
#define OFF_V  (OFF_K + HWIN*KV_STRIDE)          // 8544 + 4608
#define SMEM_FLOATS (OFF_V + HWIN*KV_STRIDE)     // 17760
#define SMEM_BYTES (SMEM_FLOATS * 4)             // 71040 -> 3 CTAs/SM

typedef unsigned long long u64;

__device__ __forceinline__ u64 pk2(float lo, float hi) {
    u64 r; asm("mov.b64 %0,{%1,%2};" : "=l"(r) : "f"(lo), "f"(hi)); return r;
}
__device__ __forceinline__ void upk2(u64 p, float& lo, float& hi) {
    asm("mov.b64 {%0,%1},%2;" : "=f"(lo), "=f"(hi) : "l"(p));
}
__device__ __forceinline__ u64 ffma2(u64 a, u64 b, u64 c) {
    u64 d; asm("fma.rn.f32x2 %0,%1,%2,%3;" : "=l"(d) : "l"(a), "l"(b), "l"(c)); return d;
}
__device__ __forceinline__ u64 fmul2(u64 a, u64 b) {
    u64 d; asm("mul.rn.f32x2 %0,%1,%2;" : "=l"(d) : "l"(a), "l"(b)); return d;
}
__device__ __forceinline__ u64 fadd2(u64 a, u64 b) {
    u64 d; asm("add.rn.f32x2 %0,%1,%2;" : "=l"(d) : "l"(a), "l"(b)); return d;
}
__device__ __forceinline__ float hsum2(u64 p) { float lo, hi; upk2(p, lo, hi); return lo + hi; }
__device__ __forceinline__ u64 dup2(float v) { return pk2(v, v); }
__device__ __forceinline__ float ex2f(float x) {
    float y; asm("ex2.approx.f32 %0,%1;" : "=f"(y) : "f"(x)); return y;
}

// dot of one 32-float weight row against two packed-16 token vectors
__device__ __forceinline__ void dot32x2(const float* __restrict__ w,
                                        const u64  va[16], const u64 vb[16],
                                        float& ra, float& rb) {
    const ulonglong2* wp = reinterpret_cast<const ulonglong2*>(w);
    u64 a0 = 0, a1 = 0, b0 = 0, b1 = 0;
#pragma unroll
    for (int i = 0; i < 8; i++) {
        ulonglong2 wv = wp[i];
        a0 = ffma2(wv.x, va[2 * i], a0);
        a1 = ffma2(wv.y, va[2 * i + 1], a1);
        b0 = ffma2(wv.x, vb[2 * i], b0);
        b1 = ffma2(wv.y, vb[2 * i + 1], b1);
    }
    ra = hsum2(fadd2(a0, a1));
    rb = hsum2(fadd2(b0, b1));
}

// packed layernorm over 16 pairs
__device__ __forceinline__ void ln32p(const u64 v[16], const float* __restrict__ g,
                                      const float* __restrict__ b, u64 o[16]) {
    u64 s = 0;
#pragma unroll
    for (int i = 0; i < 16; i++) s = fadd2(s, v[i]);
    float m = hsum2(s) * 0.03125f;
    u64 mneg = dup2(-m);
    u64 q = 0;
#pragma unroll
    for (int i = 0; i < 16; i++) { u64 d = fadd2(v[i], mneg); o[i] = d; q = ffma2(d, d, q); }
    float var = hsum2(q) * 0.03125f;
    u64 iv = dup2(rsqrtf(var + 1e-5f));
    const ulonglong2* gp = reinterpret_cast<const ulonglong2*>(g);
    const ulonglong2* bp = reinterpret_cast<const ulonglong2*>(b);
#pragma unroll
    for (int i = 0; i < 8; i++) {
        ulonglong2 gg = gp[i], bb = bp[i];
        o[2 * i]     = ffma2(fmul2(o[2 * i], iv), gg.x, bb.x);
        o[2 * i + 1] = ffma2(fmul2(o[2 * i + 1], iv), gg.y, bb.y);
    }
}

__device__ __forceinline__ void embed_token(const float* __restrict__ sw,
                                            const float* __restrict__ xp,
                                            int lay, float h[D_MODEL]) {
    const float p0 = xp[0], p1 = xp[1], p2 = xp[2];
#pragma unroll
    for (int c = 0; c < D_MODEL; c++) h[c] = sw[E_FPB + c] + sw[E_LEMB + lay * 32 + c];
#pragma unroll 1
    for (int k = 0; k < INDIM; k++) {
        float xk = __ldg(xp + k);
#pragma unroll
        for (int c = 0; c < D_MODEL; c++) h[c] = fmaf(xk, sw[E_FPW + c * INDIM + k], h[c]);
    }
#pragma unroll
    for (int j = 0; j < 16; j++) {
        float pr = 6.28318530717958647692f *
                   (p0 * sw[E_FB + j] + p1 * sw[E_FB + 16 + j] + p2 * sw[E_FB + 32 + j]);
        float sn, cs;
        sincosf(pr, &sn, &cs);
        h[j] += sn;
        h[j + 16] += cs;
    }
}

__global__ void __launch_bounds__(128, 3) spai_kernel(
    const float* __restrict__ x, const int* __restrict__ layers,
    const float* __restrict__ fpw, const float* __restrict__ fpb,
    const float* __restrict__ lemb, const float* __restrict__ fB,
    const float* __restrict__ ipw, const float* __restrict__ ipb,
    const float* __restrict__ opw, const float* __restrict__ opb,
    const float* __restrict__ g1, const float* __restrict__ b1,
    const float* __restrict__ w1, const float* __restrict__ bb1,
    const float* __restrict__ w2, const float* __restrict__ bb2,
    const float* __restrict__ g2, const float* __restrict__ b2,
    const float* __restrict__ nog, const float* __restrict__ nob,
    const float* __restrict__ hw, const float* __restrict__ hb,
    float* __restrict__ out)
{
    extern __shared__ float sw[];
    float* ks = sw + OFF_K;
    float* vs = sw + OFF_V;
    const int tid = threadIdx.x;
    const int rowA = 2 * tid, rowB = 2 * tid + 1;         // two token rows per thread
    const int mych = tid >> 6;                            // which half-window this thread's rows live in
    const int lrA = rowA & (HWIN - 1), lrB = rowB & (HWIN - 1);
    const long long ga = (long long)blockIdx.x * WIN + rowA;
    const long long gb = ga + 1;

    // ---------------- embedding weights ----------------
    for (int i = tid; i < 32 * INDIM; i += 128) sw[E_FPW + i] = fpw[i];
    if (tid < 32) sw[E_FPB + tid] = fpb[tid];
    for (int i = tid; i < 12 * 32; i += 128) sw[E_LEMB + i] = lemb[i];
    if (tid < 48) sw[E_FB + tid] = fB[tid];
    __syncthreads();

    // ---------------- embedding (2 tokens) ----------------
    float hsa[D_MODEL], hsb[D_MODEL];
    embed_token(sw, x + (size_t)ga * INDIM, layers[ga], hsa);
    embed_token(sw, x + (size_t)gb * INDIM, layers[gb], hsb);

    u64 hA[16], hB[16];
#pragma unroll
    for (int i = 0; i < 16; i++) { hA[i] = pk2(hsa[2 * i], hsa[2 * i + 1]); hB[i] = pk2(hsb[2 * i], hsb[2 * i + 1]); }

    // ---------------- transformer layers ----------------
#pragma unroll 1
    for (int li = 0; li < NLAYER; li++) {
        __syncthreads();
        for (int i = tid; i < 3072; i += 128) sw[L_IPW + i] = ipw[li * 3072 + i];
        if (tid < 96)  sw[L_IPB + tid] = ipb[li * 96 + tid];
        for (int i = tid; i < 1024; i += 128) sw[L_OPW + i] = opw[li * 1024 + i];
        if (tid < 32) {
            sw[L_OPB + tid] = opb[li * 32 + tid];
            sw[L_G1 + tid]  = g1[li * 32 + tid];
            sw[L_B1 + tid]  = b1[li * 32 + tid];
            sw[L_BB2 + tid] = bb2[li * 32 + tid];
            sw[L_G2 + tid]  = g2[li * 32 + tid];
            sw[L_B2 + tid]  = b2[li * 32 + tid];
        }
        for (int i = tid; i < 2048; i += 128) sw[L_W1 + i] = w1[li * 2048 + i];
        if (tid < 64)  sw[L_BB1 + tid] = bb1[li * 64 + tid];
        for (int i = tid; i < 2048; i += 128) {
            int c = i >> 6, f = i & 63;
            sw[L_W2T + f * 32 + c] = w2[li * 2048 + i];
        }
        __syncthreads();

        // ----- q for own tokens (all threads) -----
        // (1/sqrt(8)) * log2(e) folded into q so softmax uses raw ex2
        const float rs2 = 0.51006464544565f;
        u64 qA[16], qB[16];
#pragma unroll 2
        for (int o = 0; o < 32; o += 2) {
            float a0, b0, a1, b1v;
            dot32x2(sw + L_IPW + o * 32, hA, hB, a0, b0);
            dot32x2(sw + L_IPW + (o + 1) * 32, hA, hB, a1, b1v);
            float i0 = sw[L_IPB + o], i1 = sw[L_IPB + o + 1];
            qA[o >> 1] = pk2((a0 + i0) * rs2, (a1 + i1) * rs2);
            qB[o >> 1] = pk2((b0 + i0) * rs2, (b1v + i1) * rs2);
        }

        // ----- attention accumulators persist across both half-window chunks -----
        u64 oaA[16], oaB[16];
#pragma unroll
        for (int i = 0; i < 16; i++) { oaA[i] = 0; oaB[i] = 0; }
        float la[NHEAD] = {0.f, 0.f, 0.f, 0.f};
        float lb[NHEAD] = {0.f, 0.f, 0.f, 0.f};

#pragma unroll 1
        for (int ch = 0; ch < 2; ch++) {
            // owning half of the threads computes + stores K/V for this chunk
            if (mych == ch) {
#pragma unroll 2
                for (int o = 32; o < 96; o += 4) {
                    float ta[4], tb[4];
#pragma unroll
                    for (int u = 0; u < 4; u++) {
                        dot32x2(sw + L_IPW + (o + u) * 32, hA, hB, ta[u], tb[u]);
                        float bi = sw[L_IPB + o + u];
                        ta[u] += bi; tb[u] += bi;
                    }
                    float* dst = (o < 64) ? ks : vs;
                    int c = (o < 64) ? (o - 32) : (o - 64);
                    *reinterpret_cast<float4*>(dst + lrA * KV_STRIDE + c) = make_float4(ta[0], ta[1], ta[2], ta[3]);
                    *reinterpret_cast<float4*>(dst + lrB * KV_STRIDE + c) = make_float4(tb[0], tb[1], tb[2], tb[3]);
                }
            }
            __syncthreads();

            // everyone accumulates over this 128-row chunk
#pragma unroll 2
            for (int j = 0; j < HWIN; j++) {
                const ulonglong2* kp = reinterpret_cast<const ulonglong2*>(ks + j * KV_STRIDE);
                const ulonglong2* vp = reinterpret_cast<const ulonglong2*>(vs + j * KV_STRIDE);
#pragma unroll
                for (int hh = 0; hh < NHEAD; hh++) {
                    ulonglong2 kA = kp[2 * hh], kB = kp[2 * hh + 1];
                    u64 sa = fmul2(kA.x, qA[4 * hh]);
                    sa = ffma2(kA.y, qA[4 * hh + 1], sa);
                    sa = ffma2(kB.x, qA[4 * hh + 2], sa);
                    sa = ffma2(kB.y, qA[4 * hh + 3], sa);
                    u64 sb = fmul2(kA.x, qB[4 * hh]);
                    sb = ffma2(kA.y, qB[4 * hh + 1], sb);
                    sb = ffma2(kB.x, qB[4 * hh + 2], sb);
                    sb = ffma2(kB.y, qB[4 * hh + 3], sb);
                    float pa = ex2f(hsum2(sa));
                    float pb = ex2f(hsum2(sb));
                    la[hh] += pa; lb[hh] += pb;
                    u64 ppa = dup2(pa), ppb = dup2(pb);
                    ulonglong2 vA = vp[2 * hh], vB = vp[2 * hh + 1];
                    oaA[4 * hh]     = ffma2(ppa, vA.x, oaA[4 * hh]);
                    oaA[4 * hh + 1] = ffma2(ppa, vA.y, oaA[4 * hh + 1]);
                    oaA[4 * hh + 2] = ffma2(ppa, vB.x, oaA[4 * hh + 2]);
                    oaA[4 * hh + 3] = ffma2(ppa, vB.y, oaA[4 * hh + 3]);
                    oaB[4 * hh]     = ffma2(ppb, vA.x, oaB[4 * hh]);
                    oaB[4 * hh + 1] = ffma2(ppb, vA.y, oaB[4 * hh + 1]);
                    oaB[4 * hh + 2] = ffma2(ppb, vB.x, oaB[4 * hh + 2]);
                    oaB[4 * hh + 3] = ffma2(ppb, vB.y, oaB[4 * hh + 3]);
                }
            }
            __syncthreads();   // chunk fully consumed before next chunk overwrites
        }

#pragma unroll
        for (int hh = 0; hh < NHEAD; hh++) {
            u64 rla = dup2(1.0f / la[hh]), rlb = dup2(1.0f / lb[hh]);
#pragma unroll
            for (int p = 0; p < 4; p++) {
                oaA[4 * hh + p] = fmul2(oaA[4 * hh + p], rla);
                oaB[4 * hh + p] = fmul2(oaB[4 * hh + p], rlb);
            }
        }

        // ----- out proj + residual + LN1 -----
        u64 t1a[16], t1b[16];
#pragma unroll 2
        for (int c = 0; c < 32; c += 2) {
            float x0a, x0b, x1a, x1b;
            dot32x2(sw + L_OPW + c * 32, oaA, oaB, x0a, x0b);
            dot32x2(sw + L_OPW + (c + 1) * 32, oaA, oaB, x1a, x1b);
            float o0 = sw[L_OPB + c], o1 = sw[L_OPB + c + 1];
            t1a[c >> 1] = fadd2(hA[c >> 1], pk2(x0a + o0, x1a + o1));
            t1b[c >> 1] = fadd2(hB[c >> 1], pk2(x0b + o0, x1b + o1));
        }
        ln32p(t1a, sw + L_G1, sw + L_B1, hA);
        ln32p(t1b, sw + L_G1, sw + L_B1, hB);

        // ----- FF -----
        u64 f2a[16], f2b[16];
        {
            const ulonglong2* bp = reinterpret_cast<const ulonglong2*>(sw + L_BB2);
#pragma unroll
            for (int i = 0; i < 8; i++) {
                ulonglong2 bb = bp[i];
                f2a[2 * i] = bb.x; f2a[2 * i + 1] = bb.y;
                f2b[2 * i] = bb.x; f2b[2 * i + 1] = bb.y;
            }
        }
#pragma unroll 2
        for (int f = 0; f < DFF; f++) {
            float ta, tb;
            dot32x2(sw + L_W1 + f * 32, hA, hB, ta, tb);
            float bi = sw[L_BB1 + f];
            ta += bi; tb += bi;
            float gla = 0.5f * ta * (1.0f + erff(ta * 0.70710678118654752440f));
            float glb = 0.5f * tb * (1.0f + erff(tb * 0.70710678118654752440f));
            u64 gga = dup2(gla), ggb = dup2(glb);
            const ulonglong2* wp = reinterpret_cast<const ulonglong2*>(sw + L_W2T + f * 32);
#pragma unroll
            for (int i = 0; i < 8; i++) {
                ulonglong2 w2v = wp[i];
                f2a[2 * i]     = ffma2(gga, w2v.x, f2a[2 * i]);
                f2a[2 * i + 1] = ffma2(gga, w2v.y, f2a[2 * i + 1]);
                f2b[2 * i]     = ffma2(ggb, w2v.x, f2b[2 * i]);
                f2b[2 * i + 1] = ffma2(ggb, w2v.y, f2b[2 * i + 1]);
            }
        }
        u64 t2a[16], t2b[16];
#pragma unroll
        for (int i = 0; i < 16; i++) { t2a[i] = fadd2(hA[i], f2a[i]); t2b[i] = fadd2(hB[i], f2b[i]); }
        ln32p(t2a, sw + L_G2, sw + L_B2, hA);
        ln32p(t2b, sw + L_G2, sw + L_B2, hB);
    }

    // ---------------- final LN + head ----------------
    __syncthreads();
    if (tid < 32) { sw[H_NOG + tid] = nog[tid]; sw[H_NOB + tid] = nob[tid]; }
    for (int i = tid; i < HOUT * 32; i += 128) sw[H_HW + i] = hw[i];
    if (tid < HOUT) sw[H_HB + tid] = hb[tid];
    __syncthreads();

    u64 na[16], nb[16];
    ln32p(hA, sw + H_NOG, sw + H_NOB, na);
    ln32p(hB, sw + H_NOG, sw + H_NOB, nb);

    float* outA = out + (size_t)ga * HOUT;
    float* outB = out + (size_t)gb * HOUT;
#pragma unroll 1
    for (int c = 0; c < HOUT; c++) {
        float ta, tb;
        dot32x2(sw + H_HW + c * 32, na, nb, ta, tb);
        float bi = sw[H_HB + c];
        outA[c] = ta + bi;
        outB[c] = tb + bi;
    }
}

extern "C" void kernel_launch(void* const* d_in, const int* in_sizes, int n_in,
                              void* d_out, int out_size) {
    const float* x    = (const float*)d_in[0];
    const int*   lays = (const int*)d_in[1];
    const float* fpw  = (const float*)d_in[2];
    const float* fpb  = (const float*)d_in[3];
    const float* lemb = (const float*)d_in[4];
    const float* fB   = (const float*)d_in[5];
    const float* ipw  = (const float*)d_in[6];
    const float* ipb  = (const float*)d_in[7];
    const float* opw  = (const float*)d_in[8];
    const float* opb  = (const float*)d_in[9];
    const float* g1   = (const float*)d_in[10];
    const float* b1   = (const float*)d_in[11];
    const float* w1   = (const float*)d_in[12];
    const float* bb1  = (const float*)d_in[13];
    const float* w2   = (const float*)d_in[14];
    const float* bb2  = (const float*)d_in[15];
    const float* g2   = (const float*)d_in[16];
    const float* b2   = (const float*)d_in[17];
    const float* nog  = (const float*)d_in[18];
    const float* nob  = (const float*)d_in[19];
    const float* hw   = (const float*)d_in[20];
    const float* hb   = (const float*)d_in[21];
    float* out = (float*)d_out;

    const int tokens = in_sizes[0] / INDIM;
    const int grid = tokens / WIN;

    cudaFuncSetAttribute(spai_kernel, cudaFuncAttributeMaxDynamicSharedMemorySize, SMEM_BYTES);
    spai_kernel<<<grid, 128, SMEM_BYTES>>>(x, lays, fpw, fpb, lemb, fB, ipw, ipb, opw, opb,
                                           g1, b1, w1, bb1, w2, bb2, g2, b2, nog, nob, hw, hb,
                                           out);
}

// round 14
// speedup vs baseline: 1.7935x; 1.7935x over previous
#include <cuda_runtime.h>
#include <math.h>

#define D_MODEL 32
#define NHEAD 4
#define WIN 256
#define HWIN 128
#define DFF 64
#define INDIM 58
#define HOUT 25
#define NLAYER 4

// ---- shared memory layout (floats) ----
#define L_IPW  0      // 96*32
#define L_IPB  3072   // 96
#define L_OPW  3168   // 32*32
#define L_OPB  4192   // 32
#define L_G1   4224
#define L_B1   4256
#define L_W1   4288   // 64*32
#define L_BB1  6336   // 64
#define L_W2T  6400   // 64*32 (transposed lin2_w)
#define L_BB2  8448
#define L_G2   8480
#define L_B2   8512

// embedding overlay
#define E_FPW  0      // 32*58
#define E_FPB  1856
#define E_LEMB 1888   // 12*32
#define E_FB   2272   // 3*16

// head overlay
#define H_NOG  0
#define H_NOB  32
#define H_HW   64     // 25*32
#define H_HB   864

#define KV_STRIDE 36
#define OFF_K  8544
#define OFF_V  (OFF_K + HWIN*KV_STRIDE)          // 8544 + 4608
#define SMEM_FLOATS (OFF_V + HWIN*KV_STRIDE)     // 17760
#define SMEM_BYTES (SMEM_FLOATS * 4)             // 71040 -> 3 CTAs/SM

typedef unsigned long long u64;

__device__ __forceinline__ u64 pk2(float lo, float hi) {
    u64 r; asm("mov.b64 %0,{%1,%2};" : "=l"(r) : "f"(lo), "f"(hi)); return r;
}
__device__ __forceinline__ void upk2(u64 p, float& lo, float& hi) {
    asm("mov.b64 {%0,%1},%2;" : "=f"(lo), "=f"(hi) : "l"(p));
}
__device__ __forceinline__ u64 ffma2(u64 a, u64 b, u64 c) {
    u64 d; asm("fma.rn.f32x2 %0,%1,%2,%3;" : "=l"(d) : "l"(a), "l"(b), "l"(c)); return d;
}
__device__ __forceinline__ u64 fmul2(u64 a, u64 b) {
    u64 d; asm("mul.rn.f32x2 %0,%1,%2;" : "=l"(d) : "l"(a), "l"(b)); return d;
}
__device__ __forceinline__ u64 fadd2(u64 a, u64 b) {
    u64 d; asm("add.rn.f32x2 %0,%1,%2;" : "=l"(d) : "l"(a), "l"(b)); return d;
}
__device__ __forceinline__ float hsum2(u64 p) { float lo, hi; upk2(p, lo, hi); return lo + hi; }
__device__ __forceinline__ u64 dup2(float v) { return pk2(v, v); }
__device__ __forceinline__ float ex2f(float x) {
    float y; asm("ex2.approx.f32 %0,%1;" : "=f"(y) : "f"(x)); return y;
}

// dot of one 32-float weight row against two packed-16 token vectors
__device__ __forceinline__ void dot32x2(const float* __restrict__ w,
                                        const u64  va[16], const u64 vb[16],
                                        float& ra, float& rb) {
    const ulonglong2* wp = reinterpret_cast<const ulonglong2*>(w);
    u64 a0 = 0, a1 = 0, b0 = 0, b1 = 0;
#pragma unroll
    for (int i = 0; i < 8; i++) {
        ulonglong2 wv = wp[i];
        a0 = ffma2(wv.x, va[2 * i], a0);
        a1 = ffma2(wv.y, va[2 * i + 1], a1);
        b0 = ffma2(wv.x, vb[2 * i], b0);
        b1 = ffma2(wv.y, vb[2 * i + 1], b1);
    }
    ra = hsum2(fadd2(a0, a1));
    rb = hsum2(fadd2(b0, b1));
}

// packed layernorm over 16 pairs
__device__ __forceinline__ void ln32p(const u64 v[16], const float* __restrict__ g,
                                      const float* __restrict__ b, u64 o[16]) {
    u64 s = 0;
#pragma unroll
    for (int i = 0; i < 16; i++) s = fadd2(s, v[i]);
    float m = hsum2(s) * 0.03125f;
    u64 mneg = dup2(-m);
    u64 q = 0;
#pragma unroll
    for (int i = 0; i < 16; i++) { u64 d = fadd2(v[i], mneg); o[i] = d; q = ffma2(d, d, q); }
    float var = hsum2(q) * 0.03125f;
    u64 iv = dup2(rsqrtf(var + 1e-5f));
    const ulonglong2* gp = reinterpret_cast<const ulonglong2*>(g);
    const ulonglong2* bp = reinterpret_cast<const ulonglong2*>(b);
#pragma unroll
    for (int i = 0; i < 8; i++) {
        ulonglong2 gg = gp[i], bb = bp[i];
        o[2 * i]     = ffma2(fmul2(o[2 * i], iv), gg.x, bb.x);
        o[2 * i + 1] = ffma2(fmul2(o[2 * i + 1], iv), gg.y, bb.y);
    }
}

__device__ __forceinline__ void embed_token(const float* __restrict__ sw,
                                            const float* __restrict__ xp,
                                            int lay, float h[D_MODEL]) {
    const float p0 = xp[0], p1 = xp[1], p2 = xp[2];
#pragma unroll
    for (int c = 0; c < D_MODEL; c++) h[c] = sw[E_FPB + c] + sw[E_LEMB + lay * 32 + c];
#pragma unroll 1
    for (int k = 0; k < INDIM; k++) {
        float xk = __ldg(xp + k);
#pragma unroll
        for (int c = 0; c < D_MODEL; c++) h[c] = fmaf(xk, sw[E_FPW + c * INDIM + k], h[c]);
    }
#pragma unroll
    for (int j = 0; j < 16; j++) {
        float pr = 6.28318530717958647692f *
                   (p0 * sw[E_FB + j] + p1 * sw[E_FB + 16 + j] + p2 * sw[E_FB + 32 + j]);
        float sn, cs;
        sincosf(pr, &sn, &cs);
        h[j] += sn;
        h[j + 16] += cs;
    }
}

__global__ void __launch_bounds__(128, 3) spai_kernel(
    const float* __restrict__ x, const int* __restrict__ layers,
    const float* __restrict__ fpw, const float* __restrict__ fpb,
    const float* __restrict__ lemb, const float* __restrict__ fB,
    const float* __restrict__ ipw, const float* __restrict__ ipb,
    const float* __restrict__ opw, const float* __restrict__ opb,
    const float* __restrict__ g1, const float* __restrict__ b1,
    const float* __restrict__ w1, const float* __restrict__ bb1,
    const float* __restrict__ w2, const float* __restrict__ bb2,
    const float* __restrict__ g2, const float* __restrict__ b2,
    const float* __restrict__ nog, const float* __restrict__ nob,
    const float* __restrict__ hw, const float* __restrict__ hb,
    float* __restrict__ out)
{
    extern __shared__ float sw[];
    float* ks = sw + OFF_K;
    float* vs = sw + OFF_V;
    const int tid = threadIdx.x;
    const int rowA = 2 * tid, rowB = 2 * tid + 1;         // two token rows per thread
    const int mych = tid >> 6;                            // which half-window this thread's rows live in
    const int lrA = rowA & (HWIN - 1), lrB = rowB & (HWIN - 1);
    const long long ga = (long long)blockIdx.x * WIN + rowA;
    const long long gb = ga + 1;

    // ---------------- embedding weights ----------------
    for (int i = tid; i < 32 * INDIM; i += 128) sw[E_FPW + i] = fpw[i];
    if (tid < 32) sw[E_FPB + tid] = fpb[tid];
    for (int i = tid; i < 12 * 32; i += 128) sw[E_LEMB + i] = lemb[i];
    if (tid < 48) sw[E_FB + tid] = fB[tid];
    __syncthreads();

    // ---------------- embedding (2 tokens) ----------------
    float hsa[D_MODEL], hsb[D_MODEL];
    embed_token(sw, x + (size_t)ga * INDIM, layers[ga], hsa);
    embed_token(sw, x + (size_t)gb * INDIM, layers[gb], hsb);

    u64 hA[16], hB[16];
#pragma unroll
    for (int i = 0; i < 16; i++) { hA[i] = pk2(hsa[2 * i], hsa[2 * i + 1]); hB[i] = pk2(hsb[2 * i], hsb[2 * i + 1]); }

    // ---------------- transformer layers ----------------
#pragma unroll 1
    for (int li = 0; li < NLAYER; li++) {
        __syncthreads();
        for (int i = tid; i < 3072; i += 128) sw[L_IPW + i] = ipw[li * 3072 + i];
        if (tid < 96)  sw[L_IPB + tid] = ipb[li * 96 + tid];
        for (int i = tid; i < 1024; i += 128) sw[L_OPW + i] = opw[li * 1024 + i];
        if (tid < 32) {
            sw[L_OPB + tid] = opb[li * 32 + tid];
            sw[L_G1 + tid]  = g1[li * 32 + tid];
            sw[L_B1 + tid]  = b1[li * 32 + tid];
            sw[L_BB2 + tid] = bb2[li * 32 + tid];
            sw[L_G2 + tid]  = g2[li * 32 + tid];
            sw[L_B2 + tid]  = b2[li * 32 + tid];
        }
        for (int i = tid; i < 2048; i += 128) sw[L_W1 + i] = w1[li * 2048 + i];
        if (tid < 64)  sw[L_BB1 + tid] = bb1[li * 64 + tid];
        for (int i = tid; i < 2048; i += 128) {
            int c = i >> 6, f = i & 63;
            sw[L_W2T + f * 32 + c] = w2[li * 2048 + i];
        }
        __syncthreads();

        // ----- q for own tokens (all threads; unroll 1 to keep pressure low) -----
        // (1/sqrt(8)) * log2(e) folded into q so softmax uses raw ex2
        const float rs2 = 0.51006464544565f;
        u64 qA[16], qB[16];
#pragma unroll 1
        for (int o = 0; o < 32; o += 2) {
            float a0, b0, a1, b1v;
            dot32x2(sw + L_IPW + o * 32, hA, hB, a0, b0);
            dot32x2(sw + L_IPW + (o + 1) * 32, hA, hB, a1, b1v);
            float i0 = sw[L_IPB + o], i1 = sw[L_IPB + o + 1];
            qA[o >> 1] = pk2((a0 + i0) * rs2, (a1 + i1) * rs2);
            qB[o >> 1] = pk2((b0 + i0) * rs2, (b1v + i1) * rs2);
        }

        // ----- attention accumulators persist across both half-window chunks -----
        u64 oaA[16], oaB[16];
#pragma unroll
        for (int i = 0; i < 16; i++) { oaA[i] = 0; oaB[i] = 0; }
        float la[NHEAD] = {0.f, 0.f, 0.f, 0.f};
        float lb[NHEAD] = {0.f, 0.f, 0.f, 0.f};

#pragma unroll 1
        for (int ch = 0; ch < 2; ch++) {
            // owning half of the threads computes + stores K/V for this chunk
            if (mych == ch) {
#pragma unroll 1
                for (int o = 32; o < 96; o += 4) {
                    float ta[4], tb[4];
#pragma unroll
                    for (int u = 0; u < 4; u++) {
                        dot32x2(sw + L_IPW + (o + u) * 32, hA, hB, ta[u], tb[u]);
                        float bi = sw[L_IPB + o + u];
                        ta[u] += bi; tb[u] += bi;
                    }
                    float* dst = (o < 64) ? ks : vs;
                    int c = (o < 64) ? (o - 32) : (o - 64);
                    *reinterpret_cast<float4*>(dst + lrA * KV_STRIDE + c) = make_float4(ta[0], ta[1], ta[2], ta[3]);
                    *reinterpret_cast<float4*>(dst + lrB * KV_STRIDE + c) = make_float4(tb[0], tb[1], tb[2], tb[3]);
                }
            }
            __syncthreads();

            // everyone accumulates over this 128-row chunk (unroll 1: occupancy hides latency)
#pragma unroll 1
            for (int j = 0; j < HWIN; j++) {
                const ulonglong2* kp = reinterpret_cast<const ulonglong2*>(ks + j * KV_STRIDE);
                const ulonglong2* vp = reinterpret_cast<const ulonglong2*>(vs + j * KV_STRIDE);
#pragma unroll
                for (int hh = 0; hh < NHEAD; hh++) {
                    ulonglong2 kA = kp[2 * hh], kB = kp[2 * hh + 1];
                    u64 sa = fmul2(kA.x, qA[4 * hh]);
                    sa = ffma2(kA.y, qA[4 * hh + 1], sa);
                    sa = ffma2(kB.x, qA[4 * hh + 2], sa);
                    sa = ffma2(kB.y, qA[4 * hh + 3], sa);
                    u64 sb = fmul2(kA.x, qB[4 * hh]);
                    sb = ffma2(kA.y, qB[4 * hh + 1], sb);
                    sb = ffma2(kB.x, qB[4 * hh + 2], sb);
                    sb = ffma2(kB.y, qB[4 * hh + 3], sb);
                    float pa = ex2f(hsum2(sa));
                    float pb = ex2f(hsum2(sb));
                    la[hh] += pa; lb[hh] += pb;
                    u64 ppa = dup2(pa), ppb = dup2(pb);
                    ulonglong2 vA = vp[2 * hh], vB = vp[2 * hh + 1];
                    oaA[4 * hh]     = ffma2(ppa, vA.x, oaA[4 * hh]);
                    oaA[4 * hh + 1] = ffma2(ppa, vA.y, oaA[4 * hh + 1]);
                    oaA[4 * hh + 2] = ffma2(ppa, vB.x, oaA[4 * hh + 2]);
                    oaA[4 * hh + 3] = ffma2(ppa, vB.y, oaA[4 * hh + 3]);
                    oaB[4 * hh]     = ffma2(ppb, vA.x, oaB[4 * hh]);
                    oaB[4 * hh + 1] = ffma2(ppb, vA.y, oaB[4 * hh + 1]);
                    oaB[4 * hh + 2] = ffma2(ppb, vB.x, oaB[4 * hh + 2]);
                    oaB[4 * hh + 3] = ffma2(ppb, vB.y, oaB[4 * hh + 3]);
                }
            }
            __syncthreads();   // chunk fully consumed before next chunk overwrites
        }

#pragma unroll
        for (int hh = 0; hh < NHEAD; hh++) {
            u64 rla = dup2(1.0f / la[hh]), rlb = dup2(1.0f / lb[hh]);
#pragma unroll
            for (int p = 0; p < 4; p++) {
                oaA[4 * hh + p] = fmul2(oaA[4 * hh + p], rla);
                oaB[4 * hh + p] = fmul2(oaB[4 * hh + p], rlb);
            }
        }

        // ----- out proj + residual + LN1 -----
        u64 t1a[16], t1b[16];
#pragma unroll 1
        for (int c = 0; c < 32; c += 2) {
            float x0a, x0b, x1a, x1b;
            dot32x2(sw + L_OPW + c * 32, oaA, oaB, x0a, x0b);
            dot32x2(sw + L_OPW + (c + 1) * 32, oaA, oaB, x1a, x1b);
            float o0 = sw[L_OPB + c], o1 = sw[L_OPB + c + 1];
            t1a[c >> 1] = fadd2(hA[c >> 1], pk2(x0a + o0, x1a + o1));
            t1b[c >> 1] = fadd2(hB[c >> 1], pk2(x0b + o0, x1b + o1));
        }
        ln32p(t1a, sw + L_G1, sw + L_B1, hA);
        ln32p(t1b, sw + L_G1, sw + L_B1, hB);

        // ----- FF -----
        u64 f2a[16], f2b[16];
        {
            const ulonglong2* bp = reinterpret_cast<const ulonglong2*>(sw + L_BB2);
#pragma unroll
            for (int i = 0; i < 8; i++) {
                ulonglong2 bb = bp[i];
                f2a[2 * i] = bb.x; f2a[2 * i + 1] = bb.y;
                f2b[2 * i] = bb.x; f2b[2 * i + 1] = bb.y;
            }
        }
#pragma unroll 1
        for (int f = 0; f < DFF; f++) {
            float ta, tb;
            dot32x2(sw + L_W1 + f * 32, hA, hB, ta, tb);
            float bi = sw[L_BB1 + f];
            ta += bi; tb += bi;
            float gla = 0.5f * ta * (1.0f + erff(ta * 0.70710678118654752440f));
            float glb = 0.5f * tb * (1.0f + erff(tb * 0.70710678118654752440f));
            u64 gga = dup2(gla), ggb = dup2(glb);
            const ulonglong2* wp = reinterpret_cast<const ulonglong2*>(sw + L_W2T + f * 32);
#pragma unroll
            for (int i = 0; i < 8; i++) {
                ulonglong2 w2v = wp[i];
                f2a[2 * i]     = ffma2(gga, w2v.x, f2a[2 * i]);
                f2a[2 * i + 1] = ffma2(gga, w2v.y, f2a[2 * i + 1]);
                f2b[2 * i]     = ffma2(ggb, w2v.x, f2b[2 * i]);
                f2b[2 * i + 1] = ffma2(ggb, w2v.y, f2b[2 * i + 1]);
            }
        }
        u64 t2a[16], t2b[16];
#pragma unroll
        for (int i = 0; i < 16; i++) { t2a[i] = fadd2(hA[i], f2a[i]); t2b[i] = fadd2(hB[i], f2b[i]); }
        ln32p(t2a, sw + L_G2, sw + L_B2, hA);
        ln32p(t2b, sw + L_G2, sw + L_B2, hB);
    }

    // ---------------- final LN + head ----------------
    __syncthreads();
    if (tid < 32) { sw[H_NOG + tid] = nog[tid]; sw[H_NOB + tid] = nob[tid]; }
    for (int i = tid; i < HOUT * 32; i += 128) sw[H_HW + i] = hw[i];
    if (tid < HOUT) sw[H_HB + tid] = hb[tid];
    __syncthreads();

    u64 na[16], nb[16];
    ln32p(hA, sw + H_NOG, sw + H_NOB, na);
    ln32p(hB, sw + H_NOG, sw + H_NOB, nb);

    float* outA = out + (size_t)ga * HOUT;
    float* outB = out + (size_t)gb * HOUT;
#pragma unroll 1
    for (int c = 0; c < HOUT; c++) {
        float ta, tb;
        dot32x2(sw + H_HW + c * 32, na, nb, ta, tb);
        float bi = sw[H_HB + c];
        outA[c] = ta + bi;
        outB[c] = tb + bi;
    }
}

extern "C" void kernel_launch(void* const* d_in, const int* in_sizes, int n_in,
                              void* d_out, int out_size) {
    const float* x    = (const float*)d_in[0];
    const int*   lays = (const int*)d_in[1];
    const float* fpw  = (const float*)d_in[2];
    const float* fpb  = (const float*)d_in[3];
    const float* lemb = (const float*)d_in[4];
    const float* fB   = (const float*)d_in[5];
    const float* ipw  = (const float*)d_in[6];
    const float* ipb  = (const float*)d_in[7];
    const float* opw  = (const float*)d_in[8];
    const float* opb  = (const float*)d_in[9];
    const float* g1   = (const float*)d_in[10];
    const float* b1   = (const float*)d_in[11];
    const float* w1   = (const float*)d_in[12];
    const float* bb1  = (const float*)d_in[13];
    const float* w2   = (const float*)d_in[14];
    const float* bb2  = (const float*)d_in[15];
    const float* g2   = (const float*)d_in[16];
    const float* b2   = (const float*)d_in[17];
    const float* nog  = (const float*)d_in[18];
    const float* nob  = (const float*)d_in[19];
    const float* hw   = (const float*)d_in[20];
    const float* hb   = (const float*)d_in[21];
    float* out = (float*)d_out;

    const int tokens = in_sizes[0] / INDIM;
    const int grid = tokens / WIN;

    cudaFuncSetAttribute(spai_kernel, cudaFuncAttributeMaxDynamicSharedMemorySize, SMEM_BYTES);
    spai_kernel<<<grid, 128, SMEM_BYTES>>>(x, lays, fpw, fpb, lemb, fB, ipw, ipb, opw, opb,
                                           g1, b1, w1, bb1, w2, bb2, g2, b2, nog, nob, hw, hb,
                                           out);
}

// round 15
// speedup vs baseline: 5.7016x; 3.1790x over previous
#include <cuda_runtime.h>
#include <math.h>

#define D_MODEL 32
#define NHEAD 4
#define WIN 256
#define DFF 64
#define INDIM 58
#define HOUT 25
#define NLAYER 4

// ---- shared memory layout (floats) ----
#define L_IPW  0      // 96*32
#define L_IPB  3072   // 96
#define L_OPW  3168   // 32*32
#define L_OPB  4192   // 32
#define L_G1   4224
#define L_B1   4256
#define L_W1   4288   // 64*32
#define L_BB1  6336   // 64
#define L_W2T  6400   // 64*32 (transposed lin2_w)
#define L_BB2  8448
#define L_G2   8480
#define L_B2   8512

// embedding overlay
#define E_FPW  0      // 32*58
#define E_FPB  1856
#define E_LEMB 1888   // 12*32
#define E_FB   2272   // 3*16

// head overlay
#define H_NOG  0
#define H_NOB  32
#define H_HW   64     // 25*32
#define H_HB   864

#define KV_STRIDE 36
#define OFF_K  8544
#define OFF_V  (OFF_K + WIN*KV_STRIDE)
#define SMEM_FLOATS (OFF_V + WIN*KV_STRIDE)   // 26976
#define SMEM_BYTES (SMEM_FLOATS * 4)          // 107904 -> 2 CTAs/SM, 16 warps

typedef unsigned long long u64;

__device__ __forceinline__ u64 pk2(float lo, float hi) {
    u64 r; asm("mov.b64 %0,{%1,%2};" : "=l"(r) : "f"(lo), "f"(hi)); return r;
}
__device__ __forceinline__ void upk2(u64 p, float& lo, float& hi) {
    asm("mov.b64 {%0,%1},%2;" : "=f"(lo), "=f"(hi) : "l"(p));
}
__device__ __forceinline__ u64 ffma2(u64 a, u64 b, u64 c) {
    u64 d; asm("fma.rn.f32x2 %0,%1,%2,%3;" : "=l"(d) : "l"(a), "l"(b), "l"(c)); return d;
}
__device__ __forceinline__ u64 fmul2(u64 a, u64 b) {
    u64 d; asm("mul.rn.f32x2 %0,%1,%2;" : "=l"(d) : "l"(a), "l"(b)); return d;
}
__device__ __forceinline__ u64 fadd2(u64 a, u64 b) {
    u64 d; asm("add.rn.f32x2 %0,%1,%2;" : "=l"(d) : "l"(a), "l"(b)); return d;
}
__device__ __forceinline__ float hsum2(u64 p) { float lo, hi; upk2(p, lo, hi); return lo + hi; }
__device__ __forceinline__ u64 dup2(float v) { return pk2(v, v); }
__device__ __forceinline__ float ex2f(float x) {
    float y; asm("ex2.approx.f32 %0,%1;" : "=f"(y) : "f"(x)); return y;
}

// dot of one 32-float weight row against two packed-16 token vectors
__device__ __forceinline__ void dot32x2(const float* __restrict__ w,
                                        const u64  va[16], const u64 vb[16],
                                        float& ra, float& rb) {
    const ulonglong2* wp = reinterpret_cast<const ulonglong2*>(w);
    u64 a0 = 0, a1 = 0, b0 = 0, b1 = 0;
#pragma unroll
    for (int i = 0; i < 8; i++) {
        ulonglong2 wv = wp[i];
        a0 = ffma2(wv.x, va[2 * i], a0);
        a1 = ffma2(wv.y, va[2 * i + 1], a1);
        b0 = ffma2(wv.x, vb[2 * i], b0);
        b1 = ffma2(wv.y, vb[2 * i + 1], b1);
    }
    ra = hsum2(fadd2(a0, a1));
    rb = hsum2(fadd2(b0, b1));
}

// dot of one 32-float weight row against one packed-16 vector
__device__ __forceinline__ float dot32p(const float* w, const u64 v[16]) {
    const ulonglong2* wp = reinterpret_cast<const ulonglong2*>(w);
    u64 a0 = 0, a1 = 0;
#pragma unroll
    for (int i = 0; i < 8; i++) {
        ulonglong2 wv = wp[i];
        a0 = ffma2(wv.x, v[2 * i], a0);
        a1 = ffma2(wv.y, v[2 * i + 1], a1);
    }
    return hsum2(fadd2(a0, a1));
}

// packed layernorm over 16 pairs
__device__ __forceinline__ void ln32p(const u64 v[16], const float* __restrict__ g,
                                      const float* __restrict__ b, u64 o[16]) {
    u64 s = 0;
#pragma unroll
    for (int i = 0; i < 16; i++) s = fadd2(s, v[i]);
    float m = hsum2(s) * 0.03125f;
    u64 mneg = dup2(-m);
    u64 q = 0;
#pragma unroll
    for (int i = 0; i < 16; i++) { u64 d = fadd2(v[i], mneg); o[i] = d; q = ffma2(d, d, q); }
    float var = hsum2(q) * 0.03125f;
    u64 iv = dup2(rsqrtf(var + 1e-5f));
    const ulonglong2* gp = reinterpret_cast<const ulonglong2*>(g);
    const ulonglong2* bp = reinterpret_cast<const ulonglong2*>(b);
#pragma unroll
    for (int i = 0; i < 8; i++) {
        ulonglong2 gg = gp[i], bb = bp[i];
        o[2 * i]     = ffma2(fmul2(o[2 * i], iv), gg.x, bb.x);
        o[2 * i + 1] = ffma2(fmul2(o[2 * i + 1], iv), gg.y, bb.y);
    }
}

__device__ __forceinline__ void embed_token(const float* __restrict__ sw,
                                            const float* __restrict__ xp,
                                            int lay, float h[D_MODEL]) {
    const float p0 = xp[0], p1 = xp[1], p2 = xp[2];
#pragma unroll
    for (int c = 0; c < D_MODEL; c++) h[c] = sw[E_FPB + c] + sw[E_LEMB + lay * 32 + c];
#pragma unroll 1
    for (int k = 0; k < INDIM; k++) {
        float xk = __ldg(xp + k);
#pragma unroll
        for (int c = 0; c < D_MODEL; c++) h[c] = fmaf(xk, sw[E_FPW + c * INDIM + k], h[c]);
    }
#pragma unroll
    for (int j = 0; j < 16; j++) {
        float pr = 6.28318530717958647692f *
                   (p0 * sw[E_FB + j] + p1 * sw[E_FB + 16 + j] + p2 * sw[E_FB + 32 + j]);
        float sn, cs;
        sincosf(pr, &sn, &cs);
        h[j] += sn;
        h[j + 16] += cs;
    }
}

__global__ void __launch_bounds__(256, 2) spai_kernel(
    const float* __restrict__ x, const int* __restrict__ layers,
    const float* __restrict__ fpw, const float* __restrict__ fpb,
    const float* __restrict__ lemb, const float* __restrict__ fB,
    const float* __restrict__ ipw, const float* __restrict__ ipb,
    const float* __restrict__ opw, const float* __restrict__ opb,
    const float* __restrict__ g1, const float* __restrict__ b1,
    const float* __restrict__ w1, const float* __restrict__ bb1,
    const float* __restrict__ w2, const float* __restrict__ bb2,
    const float* __restrict__ g2, const float* __restrict__ b2,
    const float* __restrict__ nog, const float* __restrict__ nob,
    const float* __restrict__ hw, const float* __restrict__ hb,
    float* __restrict__ out)
{
    extern __shared__ float sw[];
    float* ks = sw + OFF_K;
    float* vs = sw + OFF_V;
    const int tid = threadIdx.x;
    const int g = tid >> 7;              // head-group: heads [2g, 2g+2)
    const int t = tid & 127;             // token-pair index
    const int tok0 = 2 * t, tok1 = 2 * t + 1;
    const int ownTok = tok0 + g;         // token this thread owns for O/FF/head
    const int ptok   = tok0 + (1 - g);
    const int off = 16 * g;              // float col offset of this head-pair
    const long long gOwn = (long long)blockIdx.x * WIN + ownTok;

    // ---------------- embedding weights ----------------
    for (int i = tid; i < 32 * INDIM; i += 256) sw[E_FPW + i] = fpw[i];
    if (tid < 32) sw[E_FPB + tid] = fpb[tid];
    for (int i = tid; i < 12 * 32; i += 256) sw[E_LEMB + i] = lemb[i];
    if (tid < 48) sw[E_FB + tid] = fB[tid];
    __syncthreads();

    // ---------------- embedding (1 token per thread) ----------------
    u64 hOwn[16];
    {
        float hs[D_MODEL];
        embed_token(sw, x + (size_t)gOwn * INDIM, layers[gOwn], hs);
#pragma unroll
        for (int i = 0; i < 16; i++) hOwn[i] = pk2(hs[2 * i], hs[2 * i + 1]);
        ulonglong2* hbp = reinterpret_cast<ulonglong2*>(vs + ownTok * KV_STRIDE);
#pragma unroll
        for (int i = 0; i < 8; i++) hbp[i] = make_ulonglong2(hOwn[2 * i], hOwn[2 * i + 1]);
    }
    __syncthreads();   // hbuf visible

    volatile u64 hst[16];   // deliberate cold local stash for hOwn during attention

    const float rs2 = 0.51006464544565f;   // (1/sqrt(8))*log2(e) folded into q

    // ---------------- transformer layers ----------------
#pragma unroll 1
    for (int li = 0; li < NLAYER; li++) {
        // ----- weight load + partner-h read (hbuf in V region, pre-sync) -----
        for (int i = tid; i < 3072; i += 256) sw[L_IPW + i] = ipw[li * 3072 + i];
        if (tid < 96)  sw[L_IPB + tid] = ipb[li * 96 + tid];
        for (int i = tid; i < 1024; i += 256) sw[L_OPW + i] = opw[li * 1024 + i];
        if (tid < 32) {
            sw[L_OPB + tid] = opb[li * 32 + tid];
            sw[L_G1 + tid]  = g1[li * 32 + tid];
            sw[L_B1 + tid]  = b1[li * 32 + tid];
            sw[L_BB2 + tid] = bb2[li * 32 + tid];
            sw[L_G2 + tid]  = g2[li * 32 + tid];
            sw[L_B2 + tid]  = b2[li * 32 + tid];
        }
        for (int i = tid; i < 2048; i += 256) sw[L_W1 + i] = w1[li * 2048 + i];
        if (tid < 64)  sw[L_BB1 + tid] = bb1[li * 64 + tid];
        for (int i = tid; i < 2048; i += 256) {
            int c = i >> 6, f = i & 63;
            sw[L_W2T + f * 32 + c] = w2[li * 2048 + i];
        }
        u64 hP[16];
        {
            const ulonglong2* hp = reinterpret_cast<const ulonglong2*>(vs + ptok * KV_STRIDE);
#pragma unroll
            for (int i = 0; i < 8; i++) { ulonglong2 w = hp[i]; hP[2 * i] = w.x; hP[2 * i + 1] = w.y; }
        }
        __syncthreads();   // A: weights ready; all hbuf reads done (V gets overwritten below)

        // build token-ordered h (hT0 = token 2t, hT1 = token 2t+1); stash own h
        u64 hT0[16], hT1[16];
        if (g == 0) {
#pragma unroll
            for (int i = 0; i < 16; i++) { hT0[i] = hOwn[i]; hT1[i] = hP[i]; }
        } else {
#pragma unroll
            for (int i = 0; i < 16; i++) { hT0[i] = hP[i]; hT1[i] = hOwn[i]; }
        }
#pragma unroll
        for (int i = 0; i < 16; i++) hst[i] = hOwn[i];

        // ----- q for this head-pair, both tokens -----
        u64 qT0[8], qT1[8];
#pragma unroll 1
        for (int oi = 0; oi < 16; oi += 2) {
            float a0, b0, a1, b1v;
            dot32x2(sw + L_IPW + (off + oi) * 32, hT0, hT1, a0, b0);
            dot32x2(sw + L_IPW + (off + oi + 1) * 32, hT0, hT1, a1, b1v);
            float i0 = sw[L_IPB + off + oi], i1 = sw[L_IPB + off + oi + 1];
            qT0[oi >> 1] = pk2((a0 + i0) * rs2, (a1 + i1) * rs2);
            qT1[oi >> 1] = pk2((b0 + i0) * rs2, (b1v + i1) * rs2);
        }
        // ----- K cols [off,off+16) for both tokens -----
#pragma unroll 1
        for (int kk = 0; kk < 16; kk += 4) {
            float ta[4], tb[4];
#pragma unroll
            for (int u = 0; u < 4; u++) {
                dot32x2(sw + L_IPW + (32 + off + kk + u) * 32, hT0, hT1, ta[u], tb[u]);
                float bi = sw[L_IPB + 32 + off + kk + u];
                ta[u] += bi; tb[u] += bi;
            }
            *reinterpret_cast<float4*>(ks + tok0 * KV_STRIDE + off + kk) = make_float4(ta[0], ta[1], ta[2], ta[3]);
            *reinterpret_cast<float4*>(ks + tok1 * KV_STRIDE + off + kk) = make_float4(tb[0], tb[1], tb[2], tb[3]);
        }
        // ----- V cols [off,off+16) for both tokens -----
#pragma unroll 1
        for (int kk = 0; kk < 16; kk += 4) {
            float ta[4], tb[4];
#pragma unroll
            for (int u = 0; u < 4; u++) {
                dot32x2(sw + L_IPW + (64 + off + kk + u) * 32, hT0, hT1, ta[u], tb[u]);
                float bi = sw[L_IPB + 64 + off + kk + u];
                ta[u] += bi; tb[u] += bi;
            }
            *reinterpret_cast<float4*>(vs + tok0 * KV_STRIDE + off + kk) = make_float4(ta[0], ta[1], ta[2], ta[3]);
            *reinterpret_cast<float4*>(vs + tok1 * KV_STRIDE + off + kk) = make_float4(tb[0], tb[1], tb[2], tb[3]);
        }
        __syncthreads();   // B: K/V complete

        // ----- attention: 2 heads x 2 tokens per thread -----
        u64 oaT0[8], oaT1[8];
#pragma unroll
        for (int i = 0; i < 8; i++) { oaT0[i] = 0; oaT1[i] = 0; }
        float l0a = 0.f, l0b = 0.f, l1a = 0.f, l1b = 0.f;

#pragma unroll 1
        for (int j = 0; j < WIN; j++) {
            const ulonglong2* kp = reinterpret_cast<const ulonglong2*>(ks + j * KV_STRIDE + off);
            const ulonglong2* vp = reinterpret_cast<const ulonglong2*>(vs + j * KV_STRIDE + off);
            ulonglong2 k0 = kp[0], k1 = kp[1], k2 = kp[2], k3 = kp[3];
            u64 s00 = fmul2(k0.x, qT0[0]);
            s00 = ffma2(k0.y, qT0[1], s00);
            s00 = ffma2(k1.x, qT0[2], s00);
            s00 = ffma2(k1.y, qT0[3], s00);
            u64 s01 = fmul2(k2.x, qT0[4]);
            s01 = ffma2(k2.y, qT0[5], s01);
            s01 = ffma2(k3.x, qT0[6], s01);
            s01 = ffma2(k3.y, qT0[7], s01);
            u64 s10 = fmul2(k0.x, qT1[0]);
            s10 = ffma2(k0.y, qT1[1], s10);
            s10 = ffma2(k1.x, qT1[2], s10);
            s10 = ffma2(k1.y, qT1[3], s10);
            u64 s11 = fmul2(k2.x, qT1[4]);
            s11 = ffma2(k2.y, qT1[5], s11);
            s11 = ffma2(k3.x, qT1[6], s11);
            s11 = ffma2(k3.y, qT1[7], s11);
            float p00 = ex2f(hsum2(s00));
            float p01 = ex2f(hsum2(s01));
            float p10 = ex2f(hsum2(s10));
            float p11 = ex2f(hsum2(s11));
            l0a += p00; l0b += p01; l1a += p10; l1b += p11;
            ulonglong2 v0 = vp[0], v1 = vp[1], v2 = vp[2], v3 = vp[3];
            u64 q00 = dup2(p00), q01 = dup2(p01), q10 = dup2(p10), q11 = dup2(p11);
            oaT0[0] = ffma2(q00, v0.x, oaT0[0]);
            oaT0[1] = ffma2(q00, v0.y, oaT0[1]);
            oaT0[2] = ffma2(q00, v1.x, oaT0[2]);
            oaT0[3] = ffma2(q00, v1.y, oaT0[3]);
            oaT0[4] = ffma2(q01, v2.x, oaT0[4]);
            oaT0[5] = ffma2(q01, v2.y, oaT0[5]);
            oaT0[6] = ffma2(q01, v3.x, oaT0[6]);
            oaT0[7] = ffma2(q01, v3.y, oaT0[7]);
            oaT1[0] = ffma2(q10, v0.x, oaT1[0]);
            oaT1[1] = ffma2(q10, v0.y, oaT1[1]);
            oaT1[2] = ffma2(q10, v1.x, oaT1[2]);
            oaT1[3] = ffma2(q10, v1.y, oaT1[3]);
            oaT1[4] = ffma2(q11, v2.x, oaT1[4]);
            oaT1[5] = ffma2(q11, v2.y, oaT1[5]);
            oaT1[6] = ffma2(q11, v3.x, oaT1[6]);
            oaT1[7] = ffma2(q11, v3.y, oaT1[7]);
        }
        __syncthreads();   // C: K/V reads done; K region reusable

        // scale by 1/l per head
        {
            u64 r0a = dup2(1.0f / l0a), r0b = dup2(1.0f / l0b);
            u64 r1a = dup2(1.0f / l1a), r1b = dup2(1.0f / l1b);
#pragma unroll
            for (int p = 0; p < 4; p++) {
                oaT0[p]     = fmul2(oaT0[p], r0a);
                oaT0[4 + p] = fmul2(oaT0[4 + p], r0b);
                oaT1[p]     = fmul2(oaT1[p], r1a);
                oaT1[4 + p] = fmul2(oaT1[4 + p], r1b);
            }
        }
        // exchange: write the partial for the token we do NOT own into K region
        {
            ulonglong2* ob = reinterpret_cast<ulonglong2*>(ks + ptok * KV_STRIDE);
            if (g == 0) {
#pragma unroll
                for (int i = 0; i < 4; i++) ob[i] = make_ulonglong2(oaT1[2 * i], oaT1[2 * i + 1]);
            } else {
#pragma unroll
                for (int i = 0; i < 4; i++) ob[i] = make_ulonglong2(oaT0[2 * i], oaT0[2 * i + 1]);
            }
        }
        __syncthreads();   // D: oa partials exchanged

        // assemble full oa for own token; restore h
        u64 oaF[16];
        {
            const ulonglong2* ib = reinterpret_cast<const ulonglong2*>(ks + ownTok * KV_STRIDE);
            if (g == 0) {
#pragma unroll
                for (int i = 0; i < 8; i++) oaF[i] = oaT0[i];
#pragma unroll
                for (int i = 0; i < 4; i++) { ulonglong2 w = ib[i]; oaF[8 + 2 * i] = w.x; oaF[9 + 2 * i] = w.y; }
            } else {
#pragma unroll
                for (int i = 0; i < 4; i++) { ulonglong2 w = ib[i]; oaF[2 * i] = w.x; oaF[1 + 2 * i] = w.y; }
#pragma unroll
                for (int i = 0; i < 8; i++) oaF[8 + i] = oaT1[i];
            }
        }
#pragma unroll
        for (int i = 0; i < 16; i++) hOwn[i] = hst[i];

        // ----- out proj + residual + LN1 (own token) -----
        u64 t1[16];
#pragma unroll 1
        for (int c = 0; c < 32; c += 2) {
            float x0 = dot32p(sw + L_OPW + c * 32, oaF) + sw[L_OPB + c];
            float x1 = dot32p(sw + L_OPW + (c + 1) * 32, oaF) + sw[L_OPB + c + 1];
            t1[c >> 1] = fadd2(hOwn[c >> 1], pk2(x0, x1));
        }
        ln32p(t1, sw + L_G1, sw + L_B1, hOwn);

        // ----- FF (own token) -----
        u64 f2[16];
        {
            const ulonglong2* bp = reinterpret_cast<const ulonglong2*>(sw + L_BB2);
#pragma unroll
            for (int i = 0; i < 8; i++) {
                ulonglong2 bb = bp[i];
                f2[2 * i] = bb.x; f2[2 * i + 1] = bb.y;
            }
        }
#pragma unroll 1
        for (int f = 0; f < DFF; f++) {
            float tv = dot32p(sw + L_W1 + f * 32, hOwn) + sw[L_BB1 + f];
            float gl = 0.5f * tv * (1.0f + erff(tv * 0.70710678118654752440f));
            u64 gg = dup2(gl);
            const ulonglong2* wp = reinterpret_cast<const ulonglong2*>(sw + L_W2T + f * 32);
#pragma unroll
            for (int i = 0; i < 8; i++) {
                ulonglong2 w2v = wp[i];
                f2[2 * i]     = ffma2(gg, w2v.x, f2[2 * i]);
                f2[2 * i + 1] = ffma2(gg, w2v.y, f2[2 * i + 1]);
            }
        }
        u64 t2[16];
#pragma unroll
        for (int i = 0; i < 16; i++) t2[i] = fadd2(hOwn[i], f2[i]);
        ln32p(t2, sw + L_G2, sw + L_B2, hOwn);

        // publish new h to hbuf (V region is dead now)
        {
            ulonglong2* hbp = reinterpret_cast<ulonglong2*>(vs + ownTok * KV_STRIDE);
#pragma unroll
            for (int i = 0; i < 8; i++) hbp[i] = make_ulonglong2(hOwn[2 * i], hOwn[2 * i + 1]);
        }
        __syncthreads();   // E: hbuf published
    }

    // ---------------- final LN + head (own token) ----------------
    if (tid < 32) { sw[H_NOG + tid] = nog[tid]; sw[H_NOB + tid] = nob[tid]; }
    for (int i = tid; i < HOUT * 32; i += 256) sw[H_HW + i] = hw[i];
    if (tid < HOUT) sw[H_HB + tid] = hb[tid];
    __syncthreads();

    u64 hn[16];
    ln32p(hOwn, sw + H_NOG, sw + H_NOB, hn);

    float* op = out + (size_t)gOwn * HOUT;
#pragma unroll 1
    for (int c = 0; c < HOUT; c++)
        op[c] = dot32p(sw + H_HW + c * 32, hn) + sw[H_HB + c];
}

extern "C" void kernel_launch(void* const* d_in, const int* in_sizes, int n_in,
                              void* d_out, int out_size) {
    const float* x    = (const float*)d_in[0];
    const int*   lays = (const int*)d_in[1];
    const float* fpw  = (const float*)d_in[2];
    const float* fpb  = (const float*)d_in[3];
    const float* lemb = (const float*)d_in[4];
    const float* fB   = (const float*)d_in[5];
    const float* ipw  = (const float*)d_in[6];
    const float* ipb  = (const float*)d_in[7];
    const float* opw  = (const float*)d_in[8];
    const float* opb  = (const float*)d_in[9];
    const float* g1   = (const float*)d_in[10];
    const float* b1   = (const float*)d_in[11];
    const float* w1   = (const float*)d_in[12];
    const float* bb1  = (const float*)d_in[13];
    const float* w2   = (const float*)d_in[14];
    const float* bb2  = (const float*)d_in[15];
    const float* g2   = (const float*)d_in[16];
    const float* b2   = (const float*)d_in[17];
    const float* nog  = (const float*)d_in[18];
    const float* nob  = (const float*)d_in[19];
    const float* hw   = (const float*)d_in[20];
    const float* hb   = (const float*)d_in[21];
    float* out = (float*)d_out;

    const int tokens = in_sizes[0] / INDIM;
    const int grid = tokens / WIN;

    cudaFuncSetAttribute(spai_kernel, cudaFuncAttributeMaxDynamicSharedMemorySize, SMEM_BYTES);
    spai_kernel<<<grid, 256, SMEM_BYTES>>>(x, lays, fpw, fpb, lemb, fB, ipw, ipb, opw, opb,
                                           g1, b1, w1, bb1, w2, bb2, g2, b2, nog, nob, hw, hb,
                                           out);
}

// round 17
// speedup vs baseline: 9.2449x; 1.6215x over previous
#include <cuda_runtime.h>
#include <math.h>

#define D_MODEL 32
#define NHEAD 4
#define WIN 256
#define DFF 64
#define INDIM 58
#define HOUT 25
#define NLAYER 4

// ---- float-indexed weight region (as R12) ----
#define L_IPW  0
#define L_IPB  3072
#define L_OPW  3168
#define L_OPB  4192
#define L_G1   4224
#define L_B1   4256
#define L_W1   4288
#define L_BB1  6336
#define L_W2T  6400
#define L_BB2  8448
#define L_G2   8480
#define L_B2   8512
#define WB_FLOATS 8544

// embedding overlay
#define E_FPW  0
#define E_FPB  1856
#define E_LEMB 1888
#define E_FB   2272

// head overlay
#define H_NOG  0
#define H_NOB  32
#define H_HW   64
#define H_HB   864

// ---- byte offsets for fp16 tensors ----
#define QB_OFF (WB_FLOATS * 4)             // 34176 : Q fp16, row stride 72 B (36 halves)
#define KB_OFF (QB_OFF + 256 * 72)          // 52608 : K fp16, row stride 72 B
#define VT_OFF (KB_OFF + 256 * 72)          // 71040 : V^T fp16, 32 rows x 528 B
#define SMEM_BYTES (VT_OFF + 32 * 528)      // 87936 -> 2 CTAs/SM
// oa buffer (fp32, 256 x 36 floats = 36864 B) overlays Q+K regions after attention

typedef unsigned long long u64;
typedef unsigned int u32;

__device__ __forceinline__ u64 pk2(float lo, float hi) {
    u64 r; asm("mov.b64 %0,{%1,%2};" : "=l"(r) : "f"(lo), "f"(hi)); return r;
}
__device__ __forceinline__ void upk2(u64 p, float& lo, float& hi) {
    asm("mov.b64 {%0,%1},%2;" : "=f"(lo), "=f"(hi) : "l"(p));
}
__device__ __forceinline__ u64 ffma2(u64 a, u64 b, u64 c) {
    u64 d; asm("fma.rn.f32x2 %0,%1,%2,%3;" : "=l"(d) : "l"(a), "l"(b), "l"(c)); return d;
}
__device__ __forceinline__ u64 fmul2(u64 a, u64 b) {
    u64 d; asm("mul.rn.f32x2 %0,%1,%2;" : "=l"(d) : "l"(a), "l"(b)); return d;
}
__device__ __forceinline__ u64 fadd2(u64 a, u64 b) {
    u64 d; asm("add.rn.f32x2 %0,%1,%2;" : "=l"(d) : "l"(a), "l"(b)); return d;
}
__device__ __forceinline__ float hsum2(u64 p) { float lo, hi; upk2(p, lo, hi); return lo + hi; }
__device__ __forceinline__ u64 dup2(float v) { return pk2(v, v); }
__device__ __forceinline__ float ex2f(float x) {
    float y; asm("ex2.approx.f32 %0,%1;" : "=f"(y) : "f"(x)); return y;
}
__device__ __forceinline__ u32 cvtf16x2(float hi, float lo) {
    u32 r; asm("cvt.rn.f16x2.f32 %0,%1,%2;" : "=r"(r) : "f"(hi), "f"(lo)); return r;
}
__device__ __forceinline__ void mma16n8k8(float& d0, float& d1, float& d2, float& d3,
                                          u32 a0, u32 a1, u32 b0,
                                          float c0, float c1, float c2, float c3) {
    asm volatile("mma.sync.aligned.m16n8k8.row.col.f32.f16.f16.f32 "
                 "{%0,%1,%2,%3},{%4,%5},{%6},{%7,%8,%9,%10};"
                 : "=f"(d0), "=f"(d1), "=f"(d2), "=f"(d3)
                 : "r"(a0), "r"(a1), "r"(b0), "f"(c0), "f"(c1), "f"(c2), "f"(c3));
}

__device__ __forceinline__ void dot32x2(const float* __restrict__ w,
                                        const u64  va[16], const u64 vb[16],
                                        float& ra, float& rb) {
    const ulonglong2* wp = reinterpret_cast<const ulonglong2*>(w);
    u64 a0 = 0, a1 = 0, b0 = 0, b1 = 0;
#pragma unroll
    for (int i = 0; i < 8; i++) {
        ulonglong2 wv = wp[i];
        a0 = ffma2(wv.x, va[2 * i], a0);
        a1 = ffma2(wv.y, va[2 * i + 1], a1);
        b0 = ffma2(wv.x, vb[2 * i], b0);
        b1 = ffma2(wv.y, vb[2 * i + 1], b1);
    }
    ra = hsum2(fadd2(a0, a1));
    rb = hsum2(fadd2(b0, b1));
}

__device__ __forceinline__ void ln32p(const u64 v[16], const float* __restrict__ g,
                                      const float* __restrict__ b, u64 o[16]) {
    u64 s = 0;
#pragma unroll
    for (int i = 0; i < 16; i++) s = fadd2(s, v[i]);
    float m = hsum2(s) * 0.03125f;
    u64 mneg = dup2(-m);
    u64 q = 0;
#pragma unroll
    for (int i = 0; i < 16; i++) { u64 d = fadd2(v[i], mneg); o[i] = d; q = ffma2(d, d, q); }
    float var = hsum2(q) * 0.03125f;
    u64 iv = dup2(rsqrtf(var + 1e-5f));
    const ulonglong2* gp = reinterpret_cast<const ulonglong2*>(g);
    const ulonglong2* bp = reinterpret_cast<const ulonglong2*>(b);
#pragma unroll
    for (int i = 0; i < 8; i++) {
        ulonglong2 gg = gp[i], bb = bp[i];
        o[2 * i]     = ffma2(fmul2(o[2 * i], iv), gg.x, bb.x);
        o[2 * i + 1] = ffma2(fmul2(o[2 * i + 1], iv), gg.y, bb.y);
    }
}

__device__ __forceinline__ void embed_token(const float* __restrict__ sw,
                                            const float* __restrict__ xp,
                                            int lay, float h[D_MODEL]) {
    const float p0 = xp[0], p1 = xp[1], p2 = xp[2];
#pragma unroll
    for (int c = 0; c < D_MODEL; c++) h[c] = sw[E_FPB + c] + sw[E_LEMB + lay * 32 + c];
#pragma unroll 1
    for (int k = 0; k < INDIM; k++) {
        float xk = __ldg(xp + k);
#pragma unroll
        for (int c = 0; c < D_MODEL; c++) h[c] = fmaf(xk, sw[E_FPW + c * INDIM + k], h[c]);
    }
#pragma unroll
    for (int j = 0; j < 16; j++) {
        float pr = 6.28318530717958647692f *
                   (p0 * sw[E_FB + j] + p1 * sw[E_FB + 16 + j] + p2 * sw[E_FB + 32 + j]);
        float sn, cs;
        sincosf(pr, &sn, &cs);
        h[j] += sn;
        h[j + 16] += cs;
    }
}

__global__ void __launch_bounds__(128, 2) spai_kernel(
    const float* __restrict__ x, const int* __restrict__ layers,
    const float* __restrict__ fpw, const float* __restrict__ fpb,
    const float* __restrict__ lemb, const float* __restrict__ fB,
    const float* __restrict__ ipw, const float* __restrict__ ipb,
    const float* __restrict__ opw, const float* __restrict__ opb,
    const float* __restrict__ g1, const float* __restrict__ b1,
    const float* __restrict__ w1, const float* __restrict__ bb1,
    const float* __restrict__ w2, const float* __restrict__ bb2,
    const float* __restrict__ g2, const float* __restrict__ b2,
    const float* __restrict__ nog, const float* __restrict__ nob,
    const float* __restrict__ hw, const float* __restrict__ hb,
    float* __restrict__ out)
{
    extern __shared__ char smraw[];
    float* sw = reinterpret_cast<float*>(smraw);
    float* oab = reinterpret_cast<float*>(smraw + QB_OFF);
    const int tid = threadIdx.x;
    const int rowA = 2 * tid, rowB = 2 * tid + 1;
    const long long ga = (long long)blockIdx.x * WIN + rowA;
    const long long gb = ga + 1;
    const int wid = tid >> 5, lane = tid & 31;
    const int fg = lane >> 2, fc = lane & 3;     // fragment row-group / col-pair
    const int wbase = wid * 64;

    // ---------------- embedding weights ----------------
    for (int i = tid; i < 32 * INDIM; i += 128) sw[E_FPW + i] = fpw[i];
    if (tid < 32) sw[E_FPB + tid] = fpb[tid];
    for (int i = tid; i < 12 * 32; i += 128) sw[E_LEMB + i] = lemb[i];
    if (tid < 48) sw[E_FB + tid] = fB[tid];
    __syncthreads();

    // ---------------- embedding (2 tokens) ----------------
    float hsa[D_MODEL], hsb[D_MODEL];
    embed_token(sw, x + (size_t)ga * INDIM, layers[ga], hsa);
    embed_token(sw, x + (size_t)gb * INDIM, layers[gb], hsb);

    u64 hA[16], hB[16];
#pragma unroll
    for (int i = 0; i < 16; i++) { hA[i] = pk2(hsa[2 * i], hsa[2 * i + 1]); hB[i] = pk2(hsb[2 * i], hsb[2 * i + 1]); }

    volatile u64 hst[32];   // cold stash for h during attention

    // ---------------- transformer layers ----------------
#pragma unroll 1
    for (int li = 0; li < NLAYER; li++) {
        __syncthreads();
        for (int i = tid; i < 3072; i += 128) sw[L_IPW + i] = ipw[li * 3072 + i];
        if (tid < 96)  sw[L_IPB + tid] = ipb[li * 96 + tid];
        for (int i = tid; i < 1024; i += 128) sw[L_OPW + i] = opw[li * 1024 + i];
        if (tid < 32) {
            sw[L_OPB + tid] = opb[li * 32 + tid];
            sw[L_G1 + tid]  = g1[li * 32 + tid];
            sw[L_B1 + tid]  = b1[li * 32 + tid];
            sw[L_BB2 + tid] = bb2[li * 32 + tid];
            sw[L_G2 + tid]  = g2[li * 32 + tid];
            sw[L_B2 + tid]  = b2[li * 32 + tid];
        }
        for (int i = tid; i < 2048; i += 128) sw[L_W1 + i] = w1[li * 2048 + i];
        if (tid < 64)  sw[L_BB1 + tid] = bb1[li * 64 + tid];
        for (int i = tid; i < 2048; i += 128) {
            int c = i >> 6, f = i & 63;
            sw[L_W2T + f * 32 + c] = w2[li * 2048 + i];
        }
        __syncthreads();

        // ----- QKV: fp32 compute, fp16 store -----
        const float rs2 = 0.51006464544565f;   // (1/sqrt(8))*log2(e) into q
#pragma unroll 1
        for (int o = 0; o < 32; o += 2) {
            float a0, b0, a1, b1v;
            dot32x2(sw + L_IPW + o * 32, hA, hB, a0, b0);
            dot32x2(sw + L_IPW + (o + 1) * 32, hA, hB, a1, b1v);
            float i0 = sw[L_IPB + o], i1 = sw[L_IPB + o + 1];
            *(u32*)(smraw + QB_OFF + rowA * 72 + o * 2) = cvtf16x2((a1 + i1) * rs2, (a0 + i0) * rs2);
            *(u32*)(smraw + QB_OFF + rowB * 72 + o * 2) = cvtf16x2((b1v + i1) * rs2, (b0 + i0) * rs2);
        }
#pragma unroll 1
        for (int o = 32; o < 64; o += 2) {
            float a0, b0, a1, b1v;
            dot32x2(sw + L_IPW + o * 32, hA, hB, a0, b0);
            dot32x2(sw + L_IPW + (o + 1) * 32, hA, hB, a1, b1v);
            float i0 = sw[L_IPB + o], i1 = sw[L_IPB + o + 1];
            int kd = o - 32;
            *(u32*)(smraw + KB_OFF + rowA * 72 + kd * 2) = cvtf16x2(a1 + i1, a0 + i0);
            *(u32*)(smraw + KB_OFF + rowB * 72 + kd * 2) = cvtf16x2(b1v + i1, b0 + i0);
        }
#pragma unroll 1
        for (int o = 64; o < 96; o += 2) {
            float a0, b0, a1, b1v;
            dot32x2(sw + L_IPW + o * 32, hA, hB, a0, b0);
            dot32x2(sw + L_IPW + (o + 1) * 32, hA, hB, a1, b1v);
            float i0 = sw[L_IPB + o], i1 = sw[L_IPB + o + 1];
            int d = o - 64;
            // Vt[d][rowA], Vt[d][rowB] packed (lo = rowA)
            *(u32*)(smraw + VT_OFF + d * 528 + rowA * 2)       = cvtf16x2(b0 + i0, a0 + i0);
            *(u32*)(smraw + VT_OFF + (d + 1) * 528 + rowA * 2) = cvtf16x2(b1v + i1, a1 + i1);
        }
        __syncthreads();

        // stash h (cold during attention)
#pragma unroll
        for (int i = 0; i < 16; i++) { hst[i] = hA[i]; hst[16 + i] = hB[i]; }

        // ----- load Q A-fragments (held across the whole j loop) -----
        u32 aF[4][4][2];
#pragma unroll
        for (int mb = 0; mb < 4; mb++)
#pragma unroll
            for (int h = 0; h < 4; h++) {
                int r0 = wbase + mb * 16 + fg;
                aF[mb][h][0] = *(const u32*)(smraw + QB_OFF + r0 * 72 + (h * 8 + 2 * fc) * 2);
                aF[mb][h][1] = *(const u32*)(smraw + QB_OFF + (r0 + 8) * 72 + (h * 8 + 2 * fc) * 2);
            }

        float oaC[4][4][4];
        float lacc[4][4][2];
#pragma unroll
        for (int mb = 0; mb < 4; mb++)
#pragma unroll
            for (int h = 0; h < 4; h++) {
                oaC[mb][h][0] = 0.f; oaC[mb][h][1] = 0.f; oaC[mb][h][2] = 0.f; oaC[mb][h][3] = 0.f;
                lacc[mb][h][0] = 0.f; lacc[mb][h][1] = 0.f;
            }

        // ----- attention: tensor-core scores + PV -----
#pragma unroll 1
        for (int jt = 0; jt < 32; jt++) {
#pragma unroll
            for (int h = 0; h < 4; h++) {
                u32 bk = *(const u32*)(smraw + KB_OFF + (jt * 8 + fg) * 72 + (h * 8 + 2 * fc) * 2);
                u32 bv = *(const u32*)(smraw + VT_OFF + (h * 8 + fg) * 528 + (jt * 8 + 2 * fc) * 2);
#pragma unroll
                for (int mb = 0; mb < 4; mb++) {
                    float d0, d1, d2, d3;
                    mma16n8k8(d0, d1, d2, d3, aF[mb][h][0], aF[mb][h][1], bk,
                              0.0f, 0.0f, 0.0f, 0.0f);
                    d0 = ex2f(d0); d1 = ex2f(d1); d2 = ex2f(d2); d3 = ex2f(d3);
                    lacc[mb][h][0] += d0 + d1;
                    lacc[mb][h][1] += d2 + d3;
                    u32 p0 = cvtf16x2(d1, d0);
                    u32 p1 = cvtf16x2(d3, d2);
                    mma16n8k8(oaC[mb][h][0], oaC[mb][h][1], oaC[mb][h][2], oaC[mb][h][3],
                              p0, p1, bv,
                              oaC[mb][h][0], oaC[mb][h][1], oaC[mb][h][2], oaC[mb][h][3]);
                }
            }
        }
        __syncthreads();   // all K/Q/Vt reads complete

        // ----- normalize (quad-reduce l) + write oa to buffer -----
#pragma unroll
        for (int mb = 0; mb < 4; mb++)
#pragma unroll
            for (int h = 0; h < 4; h++) {
                float l0 = lacc[mb][h][0], l1 = lacc[mb][h][1];
                l0 += __shfl_xor_sync(0xffffffffu, l0, 1);
                l0 += __shfl_xor_sync(0xffffffffu, l0, 2);
                l1 += __shfl_xor_sync(0xffffffffu, l1, 1);
                l1 += __shfl_xor_sync(0xffffffffu, l1, 2);
                float r0 = 1.0f / l0, r1 = 1.0f / l1;
                int row = wbase + mb * 16 + fg;
                *(float2*)(oab + row * 36 + h * 8 + 2 * fc) =
                    make_float2(oaC[mb][h][0] * r0, oaC[mb][h][1] * r0);
                *(float2*)(oab + (row + 8) * 36 + h * 8 + 2 * fc) =
                    make_float2(oaC[mb][h][2] * r1, oaC[mb][h][3] * r1);
            }
        __syncthreads();   // oa buffer complete

        // ----- gather oa for own tokens; restore h -----
        u64 oaA[16], oaB[16];
        {
            const ulonglong2* pa = reinterpret_cast<const ulonglong2*>(oab + rowA * 36);
            const ulonglong2* pb = reinterpret_cast<const ulonglong2*>(oab + rowB * 36);
#pragma unroll
            for (int i = 0; i < 8; i++) {
                ulonglong2 wa = pa[i], wb = pb[i];
                oaA[2 * i] = wa.x; oaA[2 * i + 1] = wa.y;
                oaB[2 * i] = wb.x; oaB[2 * i + 1] = wb.y;
            }
        }
#pragma unroll
        for (int i = 0; i < 16; i++) { hA[i] = hst[i]; hB[i] = hst[16 + i]; }

        // ----- out proj + residual + LN1 -----
        u64 t1a[16], t1b[16];
#pragma unroll 1
        for (int c = 0; c < 32; c += 2) {
            float x0a, x0b, x1a, x1b;
            dot32x2(sw + L_OPW + c * 32, oaA, oaB, x0a, x0b);
            dot32x2(sw + L_OPW + (c + 1) * 32, oaA, oaB, x1a, x1b);
            float o0 = sw[L_OPB + c], o1 = sw[L_OPB + c + 1];
            t1a[c >> 1] = fadd2(hA[c >> 1], pk2(x0a + o0, x1a + o1));
            t1b[c >> 1] = fadd2(hB[c >> 1], pk2(x0b + o0, x1b + o1));
        }
        ln32p(t1a, sw + L_G1, sw + L_B1, hA);
        ln32p(t1b, sw + L_G1, sw + L_B1, hB);

        // ----- FF -----
        u64 f2a[16], f2b[16];
        {
            const ulonglong2* bp = reinterpret_cast<const ulonglong2*>(sw + L_BB2);
#pragma unroll
            for (int i = 0; i < 8; i++) {
                ulonglong2 bb = bp[i];
                f2a[2 * i] = bb.x; f2a[2 * i + 1] = bb.y;
                f2b[2 * i] = bb.x; f2b[2 * i + 1] = bb.y;
            }
        }
#pragma unroll 1
        for (int f = 0; f < DFF; f++) {
            float ta, tb;
            dot32x2(sw + L_W1 + f * 32, hA, hB, ta, tb);
            float bi = sw[L_BB1 + f];
            ta += bi; tb += bi;
            float gla = 0.5f * ta * (1.0f + erff(ta * 0.70710678118654752440f));
            float glb = 0.5f * tb * (1.0f + erff(tb * 0.70710678118654752440f));
            u64 gga = dup2(gla), ggb = dup2(glb);
            const ulonglong2* wp = reinterpret_cast<const ulonglong2*>(sw + L_W2T + f * 32);
#pragma unroll
            for (int i = 0; i < 8; i++) {
                ulonglong2 w2v = wp[i];
                f2a[2 * i]     = ffma2(gga, w2v.x, f2a[2 * i]);
                f2a[2 * i + 1] = ffma2(gga, w2v.y, f2a[2 * i + 1]);
                f2b[2 * i]     = ffma2(ggb, w2v.x, f2b[2 * i]);
                f2b[2 * i + 1] = ffma2(ggb, w2v.y, f2b[2 * i + 1]);
            }
        }
        u64 t2a[16], t2b[16];
#pragma unroll
        for (int i = 0; i < 16; i++) { t2a[i] = fadd2(hA[i], f2a[i]); t2b[i] = fadd2(hB[i], f2b[i]); }
        ln32p(t2a, sw + L_G2, sw + L_B2, hA);
        ln32p(t2b, sw + L_G2, sw + L_B2, hB);
    }

    // ---------------- final LN + head ----------------
    __syncthreads();
    if (tid < 32) { sw[H_NOG + tid] = nog[tid]; sw[H_NOB + tid] = nob[tid]; }
    for (int i = tid; i < HOUT * 32; i += 128) sw[H_HW + i] = hw[i];
    if (tid < HOUT) sw[H_HB + tid] = hb[tid];
    __syncthreads();

    u64 na[16], nb[16];
    ln32p(hA, sw + H_NOG, sw + H_NOB, na);
    ln32p(hB, sw + H_NOG, sw + H_NOB, nb);

    float* outA = out + (size_t)ga * HOUT;
    float* outB = out + (size_t)gb * HOUT;
#pragma unroll 1
    for (int c = 0; c < HOUT; c++) {
        float ta, tb;
        dot32x2(sw + H_HW + c * 32, na, nb, ta, tb);
        float bi = sw[H_HB + c];
        outA[c] = ta + bi;
        outB[c] = tb + bi;
    }
}

extern "C" void kernel_launch(void* const* d_in, const int* in_sizes, int n_in,
                              void* d_out, int out_size) {
    const float* x    = (const float*)d_in[0];
    const int*   lays = (const int*)d_in[1];
    const float* fpw  = (const float*)d_in[2];
    const float* fpb  = (const float*)d_in[3];
    const float* lemb = (const float*)d_in[4];
    const float* fB   = (const float*)d_in[5];
    const float* ipw  = (const float*)d_in[6];
    const float* ipb  = (const float*)d_in[7];
    const float* opw  = (const float*)d_in[8];
    const float* opb  = (const float*)d_in[9];
    const float* g1   = (const float*)d_in[10];
    const float* b1   = (const float*)d_in[11];
    const float* w1   = (const float*)d_in[12];
    const float* bb1  = (const float*)d_in[13];
    const float* w2   = (const float*)d_in[14];
    const float* bb2  = (const float*)d_in[15];
    const float* g2   = (const float*)d_in[16];
    const float* b2   = (const float*)d_in[17];
    const float* nog  = (const float*)d_in[18];
    const float* nob  = (const float*)d_in[19];
    const float* hw   = (const float*)d_in[20];
    const float* hb   = (const float*)d_in[21];
    float* out = (float*)d_out;

    const int tokens = in_sizes[0] / INDIM;
    const int grid = tokens / WIN;

    cudaFuncSetAttribute(spai_kernel, cudaFuncAttributeMaxDynamicSharedMemorySize, SMEM_BYTES);
    spai_kernel<<<grid, 128, SMEM_BYTES>>>(x, lays, fpw, fpb, lemb, fB, ipw, ipb, opw, opb,
                                           g1, b1, w1, bb1, w2, bb2, g2, b2, nog, nob, hw, hb,
                                           out);
}